// round 6
// baseline (speedup 1.0000x reference)
#include <cuda_runtime.h>
#include <cuda_bf16.h>
#include <math.h>

// Problem constants
#define BB 32
#define SS 1024
#define EE 512
#define HH 256
#define G4 1024          // 4*H

// ---------------- static scratch (no allocations) ----------------
__device__ float    g_xg[(size_t)2 * SS * G4 * BB];     // [d][t][g][b]
__device__ float    g_hh[(size_t)2 * SS * BB * HH];     // [d][t][b][k]
__device__ float    g_WT[(size_t)2 * EE * G4];          // [d][e][g]
__device__ int      g_tok[2 * SS * BB];                 // [d][t*32+b]
__device__ int      g_order[BB * SS];
__device__ int      g_counts[BB];
__device__ float    g_hprev[2][2][HH * BB];             // [d][buf][k*32+b]
__device__ unsigned g_cnt[2];

__device__ __forceinline__ float sigm(float x) { return 1.0f / (1.0f + __expf(-x)); }

// ---------------- prep: order/counts, token arrays, state reset ----------------
__global__ __launch_bounds__(1024) void k_prep(const int* __restrict__ inputs,
                                               const int* __restrict__ seqlen,
                                               const int* __restrict__ fmask)
{
    int b = blockIdx.x;
    int t = threadIdx.x;
    __shared__ int sc[SS];
    int m = (fmask[b * SS + t] != 0) ? 1 : 0;
    sc[t] = m;
    __syncthreads();
    for (int off = 1; off < SS; off <<= 1) {
        int v = (t >= off) ? sc[t - off] : 0;
        __syncthreads();
        sc[t] += v;
        __syncthreads();
    }
    if (m) g_order[b * SS + sc[t] - 1] = t;
    if (t == SS - 1) g_counts[b] = sc[t];

    int len = seqlen[b];
    g_tok[t * BB + b] = inputs[b * SS + t];
    g_tok[SS * BB + t * BB + b] = (t < len) ? inputs[b * SS + (len - 1 - t)] : 0;

    if (b == 0) {
        // zero h_prev buf0 for both directions; reset barrier counters
        for (int i = t; i < 2 * HH * BB; i += 1024) {
            int d = i / (HH * BB);
            g_hprev[d][0][i - d * HH * BB] = 0.0f;
        }
        if (t < 2) g_cnt[t] = 0u;
    }
}

// ---------------- transpose W_ih -> [e][g] for coalesced GEMM A loads ----------
__global__ __launch_bounds__(512) void k_wt(const float* __restrict__ fW,
                                            const float* __restrict__ bW)
{
    int d = blockIdx.y;
    int g = blockIdx.x;           // 0..1023
    int e = threadIdx.x;          // 0..511
    const float* W = d ? bW : fW;
    g_WT[(size_t)d * EE * G4 + (size_t)e * G4 + g] = W[(size_t)g * EE + e];
}

// ---------------- xg GEMM with fused embedding gather --------------------------
// C[d][t][g][b] = sum_e emb[tok[d][t*32+b]][e] * Wih[g][e] + bih[g] + bhh[g]
// M = 1024 (g), N = 32768 (t*32+b), K = 512. Tiles 64x64x32, 256 threads, 4x4.
__global__ __launch_bounds__(256) void k_gemm(
    const float* __restrict__ emb,
    const float* __restrict__ fbih, const float* __restrict__ fbhh,
    const float* __restrict__ bbih, const float* __restrict__ bbhh)
{
    const int d  = blockIdx.z;
    const int g0 = blockIdx.y * 64;
    const int n0 = blockIdx.x * 64;
    const float* __restrict__ WT  = g_WT + (size_t)d * EE * G4;   // [e][g]
    const int*   __restrict__ tok = g_tok + d * SS * BB;
    const float* __restrict__ bih = d ? bbih : fbih;
    const float* __restrict__ bhh = d ? bbhh : fbhh;

    __shared__ __align__(16) float As[32][64];   // [k][m]
    __shared__ __align__(16) float Bs[32][64];   // [k][n]
    __shared__ int ts[64];

    const int tid = threadIdx.x;
    if (tid < 64) ts[tid] = tok[n0 + tid];
    __syncthreads();

    float acc[4][4];
#pragma unroll
    for (int i = 0; i < 4; i++)
#pragma unroll
        for (int j = 0; j < 4; j++) acc[i][j] = 0.0f;

    const int ty = tid >> 4;      // 0..15 (m quad)
    const int tx = tid & 15;      // 0..15 (n quad)

    for (int k0 = 0; k0 < EE; k0 += 32) {
        // A tile: As[k][m] from WT[k0+k][g0+m], float4 along m
#pragma unroll
        for (int q = 0; q < 2; q++) {
            int idx = tid + q * 256;           // 0..511
            int k   = idx >> 4;                // 0..31
            int m4  = (idx & 15) << 2;         // 0..60
            float4 v = *(const float4*)(WT + (size_t)(k0 + k) * G4 + g0 + m4);
            *(float4*)&As[k][m4] = v;
        }
        // B tile: Bs[k][n] = emb[ts[n]][k0+k], float4 along k then scatter
#pragma unroll
        for (int q = 0; q < 2; q++) {
            int idx = tid + q * 256;
            int n   = idx & 63;
            int kq  = idx >> 6;                // 0..7
            float4 v = *(const float4*)(emb + (size_t)ts[n] * EE + k0 + kq * 4);
            Bs[kq * 4 + 0][n] = v.x;
            Bs[kq * 4 + 1][n] = v.y;
            Bs[kq * 4 + 2][n] = v.z;
            Bs[kq * 4 + 3][n] = v.w;
        }
        __syncthreads();
#pragma unroll
        for (int k = 0; k < 32; k++) {
            float4 a = *(float4*)&As[k][ty * 4];
            float4 b = *(float4*)&Bs[k][tx * 4];
            acc[0][0] += a.x * b.x; acc[0][1] += a.x * b.y; acc[0][2] += a.x * b.z; acc[0][3] += a.x * b.w;
            acc[1][0] += a.y * b.x; acc[1][1] += a.y * b.y; acc[1][2] += a.y * b.z; acc[1][3] += a.y * b.w;
            acc[2][0] += a.z * b.x; acc[2][1] += a.z * b.y; acc[2][2] += a.z * b.z; acc[2][3] += a.z * b.w;
            acc[3][0] += a.w * b.x; acc[3][1] += a.w * b.y; acc[3][2] += a.w * b.z; acc[3][3] += a.w * b.w;
        }
        __syncthreads();
    }

    // epilogue: add biases, store to g_xg[d][t][g][b]
    int t  = (n0 >> 5) + ((tx * 4) >> 5);    // n0 covers 2 t values
    int b0 = (tx * 4) & 31;
    size_t base_d = (size_t)d * SS * G4 * BB;
#pragma unroll
    for (int i = 0; i < 4; i++) {
        int grow = g0 + ty * 4 + i;
        float bias = bih[grow] + bhh[grow];
        float4 r;
        r.x = acc[i][0] + bias; r.y = acc[i][1] + bias;
        r.z = acc[i][2] + bias; r.w = acc[i][3] + bias;
        size_t off = base_d + (((size_t)t * G4 + grow) << 5) + b0;
        *(float4*)&g_xg[off] = r;
    }
}

// ---------------- persistent recurrence --------------------------------------
// 128 blocks: d = bx>>6, blk = bx&63. Block owns hidden units 4*blk..4*blk+3
// (16 gate rows). W_hh slice cached in SMEM for all 1024 steps.
__global__ __launch_bounds__(256) void k_rec(const float* __restrict__ fWhh,
                                             const float* __restrict__ bWhh)
{
    const int d   = blockIdx.x >> 6;
    const int blk = blockIdx.x & 63;
    const float* __restrict__ Whh = d ? bWhh : fWhh;

    __shared__ __align__(16) float Wsh[16][256];   // 16 KB
    __shared__ __align__(16) float hs[HH * BB];    // 32 KB, [k*32+b]
    float* gb = hs;                                // alias: gates buffer [16][32]

    const int tid  = threadIdx.x;
    const int w    = tid >> 5;
    const int lane = tid & 31;

    // preload W_hh slice: local row l -> global gate row (l&3)*H + blk*4 + (l>>2)
#pragma unroll
    for (int q = 0; q < 4; q++) {
        int idx = tid + q * 256;              // 0..1023
        int l   = idx >> 6;                   // 0..15
        int k4  = (idx & 63) << 2;            // 0..252
        int grow = (l & 3) * HH + blk * 4 + (l >> 2);
        *(float4*)&Wsh[l][k4] = *(const float4*)(Whh + (size_t)grow * HH + k4);
    }

    const int l0 = 2 * w, l1 = 2 * w + 1;
    const int grow0 = (l0 & 3) * HH + blk * 4 + (l0 >> 2);
    const int grow1 = (l1 & 3) * HH + blk * 4 + (l1 >> 2);
    const float* __restrict__ xgd = g_xg + (size_t)d * SS * G4 * BB;
    float* __restrict__ hhd = g_hh + (size_t)d * SS * BB * HH;
    unsigned* cnt = &g_cnt[d];

    float c = 0.0f;   // cell state for (u=tid>>5, b=tid&31), valid for tid<128
    const int cu = tid >> 5;
    const int cb = tid & 31;
    const int ck = blk * 4 + cu;

    for (int t = 0; t < SS; t++) {
        const float* rbuf = g_hprev[d][t & 1];
        float*       wbuf = g_hprev[d][(t + 1) & 1];
        // stage h(t-1): straight copy, same [k*32+b] layout
#pragma unroll
        for (int q = 0; q < 8; q++) {
            int idx = tid + q * 256;          // float4 idx 0..2047
            *(float4*)&hs[idx * 4] = *(const float4*)(rbuf + idx * 4);
        }
        __syncthreads();

        float a0 = xgd[(((size_t)t * G4 + grow0) << 5) + lane];
        float a1 = xgd[(((size_t)t * G4 + grow1) << 5) + lane];
#pragma unroll
        for (int k = 0; k < HH; k += 4) {
            float4 w0 = *(float4*)&Wsh[l0][k];
            float4 w1 = *(float4*)&Wsh[l1][k];
            float h0 = hs[(k + 0) * 32 + lane];
            float h1 = hs[(k + 1) * 32 + lane];
            float h2 = hs[(k + 2) * 32 + lane];
            float h3 = hs[(k + 3) * 32 + lane];
            a0 += h0 * w0.x + h1 * w0.y + h2 * w0.z + h3 * w0.w;
            a1 += h0 * w1.x + h1 * w1.y + h2 * w1.z + h3 * w1.w;
        }
        __syncthreads();                 // all reads of hs done before alias write
        gb[l0 * 32 + lane] = a0;
        gb[l1 * 32 + lane] = a1;
        __syncthreads();

        if (tid < 128) {
            float gi = gb[(cu * 4 + 0) * 32 + cb];
            float gf = gb[(cu * 4 + 1) * 32 + cb];
            float gg = gb[(cu * 4 + 2) * 32 + cb];
            float go = gb[(cu * 4 + 3) * 32 + cb];
            c = sigm(gf) * c + sigm(gi) * tanhf(gg);
            float h = sigm(go) * tanhf(c);
            wbuf[ck * 32 + cb] = h;
            hhd[(((size_t)t * BB + cb) << 8) + ck] = h;
        }
        __syncthreads();
        if (tid == 0) {
            asm volatile("red.release.gpu.add.u32 [%0], %1;" :: "l"(cnt), "r"(1u) : "memory");
            unsigned target = 64u * (unsigned)(t + 1);
            unsigned v;
            do {
                asm volatile("ld.acquire.gpu.u32 %0, [%1];" : "=r"(v) : "l"(cnt) : "memory");
            } while (v < target);
        }
        __syncthreads();
    }
}

// ---------------- output gather -----------------------------------------------
__global__ __launch_bounds__(128) void k_gather(float* __restrict__ out, int rows)
{
    int j = blockIdx.x;
    int b = blockIdx.y;
    int tid = threadIdx.x;
    int cnt = g_counts[b];
    size_t orow = ((size_t)b * rows + j) * 512;
    float4 v = make_float4(0.f, 0.f, 0.f, 0.f);
    if (j < cnt) {
        if (tid < 64) {
            int tf = g_order[b * SS + j];
            v = *(const float4*)(g_hh + (((size_t)tf * BB + b) << 8) + tid * 4);
        } else {
            int tb = g_order[b * SS + (cnt - 1 - j)];
            v = *(const float4*)(g_hh + ((((size_t)SS + tb) * BB + b) << 8) + (tid - 64) * 4);
        }
    }
    *(float4*)(out + orow + tid * 4) = v;
}

// ---------------- launch ------------------------------------------------------
extern "C" void kernel_launch(void* const* d_in, const int* in_sizes, int n_in,
                              void* d_out, int out_size)
{
    const int*   inputs = (const int*)d_in[0];
    const int*   seqlen = (const int*)d_in[1];
    const int*   fmask  = (const int*)d_in[2];
    // d_in[3] = bmask (unused by the reference math)
    int base = (in_sizes[4] == 1) ? 5 : 4;   // skip out_seq_length scalar if present
    const float* emb   = (const float*)d_in[base + 0];
    const float* f_Wih = (const float*)d_in[base + 1];
    const float* f_Whh = (const float*)d_in[base + 2];
    const float* f_bih = (const float*)d_in[base + 3];
    const float* f_bhh = (const float*)d_in[base + 4];
    const float* b_Wih = (const float*)d_in[base + 5];
    const float* b_Whh = (const float*)d_in[base + 6];
    const float* b_bih = (const float*)d_in[base + 7];
    const float* b_bhh = (const float*)d_in[base + 8];
    (void)n_in; (void)f_Wih; (void)b_Wih;

    int rows = out_size / (BB * 512);        // out_seq_length (== S here)

    k_prep<<<BB, SS>>>(inputs, seqlen, fmask);
    k_wt<<<dim3(G4, 2), EE>>>(f_Wih, b_Wih);
    k_gemm<<<dim3(512, 16, 2), 256>>>(emb, f_bih, f_bhh, b_bih, b_bhh);
    k_rec<<<128, 256>>>(f_Whh, b_Whh);
    k_gather<<<dim3(rows, BB), 128>>>((float*)d_out, rows);
}

// round 7
// speedup vs baseline: 1.0202x; 1.0202x over previous
#include <cuda_runtime.h>
#include <cuda_bf16.h>
#include <math.h>

// Problem constants
#define BB 32
#define SS 1024
#define EE 512
#define HH 256
#define G4 1024          // 4*H

// ---------------- static scratch (no allocations) ----------------
__device__ float    g_xg[(size_t)2 * SS * G4 * BB];     // [d][t][g][b]
__device__ float    g_hh[(size_t)2 * SS * BB * HH];     // [d][t][b][k]
__device__ int      g_tok[2 * SS * BB];                 // [d][t*32+b]
__device__ int      g_order[BB * SS];
__device__ int      g_counts[BB];
__device__ float    g_hprev[2][2][HH * BB];             // [d][buf][k*32+b]
__device__ unsigned g_cnt[2];

__device__ __forceinline__ float sigm(float x) { return 1.0f / (1.0f + __expf(-x)); }

__device__ __forceinline__ void fma2(unsigned long long &d,
                                     unsigned long long a, unsigned long long b) {
    asm("fma.rn.f32x2 %0, %1, %2, %0;" : "+l"(d) : "l"(a), "l"(b));
}
__device__ __forceinline__ unsigned long long dup2(float x) {
    unsigned long long r; asm("mov.b64 %0, {%1, %1};" : "=l"(r) : "f"(x)); return r;
}
__device__ __forceinline__ float2 unpk(unsigned long long v) {
    float2 r; asm("mov.b64 {%0, %1}, %2;" : "=f"(r.x), "=f"(r.y) : "l"(v)); return r;
}

// ---------------- prep: order/counts, token arrays, state reset ----------------
__global__ __launch_bounds__(1024) void k_prep(const int* __restrict__ inputs,
                                               const int* __restrict__ seqlen,
                                               const int* __restrict__ fmask)
{
    int b = blockIdx.x;
    int t = threadIdx.x;
    __shared__ int sc[SS];
    int m = (fmask[b * SS + t] != 0) ? 1 : 0;
    sc[t] = m;
    __syncthreads();
    for (int off = 1; off < SS; off <<= 1) {
        int v = (t >= off) ? sc[t - off] : 0;
        __syncthreads();
        sc[t] += v;
        __syncthreads();
    }
    if (m) g_order[b * SS + sc[t] - 1] = t;
    if (t == SS - 1) g_counts[b] = sc[t];

    int len = seqlen[b];
    g_tok[t * BB + b] = inputs[b * SS + t];
    g_tok[SS * BB + t * BB + b] = (t < len) ? inputs[b * SS + (len - 1 - t)] : 0;

    if (b == 0) {
        for (int i = t; i < 2 * HH * BB; i += 1024) {
            int d = i / (HH * BB);
            g_hprev[d][0][i - d * HH * BB] = 0.0f;
        }
        if (t < 2) g_cnt[t] = 0u;
    }
}

// ---------------- xg GEMM: fused embedding gather + f32x2 packed FMA -----------
// C[d][t][g][b] = sum_e emb[tok][e] * Wih[g][e] + bih[g] + bhh[g]
// M=1024(g), N=32768(t,b), K=512. Tiles 64x64x32, 256 thr, 4x4 microtile,
// accumulators packed pairwise along n in f32x2; A pre-duplicated in smem.
__global__ __launch_bounds__(256) void k_gemm(
    const float* __restrict__ emb,
    const float* __restrict__ fWih, const float* __restrict__ bWih,
    const float* __restrict__ fbih, const float* __restrict__ fbhh,
    const float* __restrict__ bbih, const float* __restrict__ bbhh)
{
    const int d  = blockIdx.z;
    const int g0 = blockIdx.y * 64;
    const int n0 = blockIdx.x * 64;
    const float* __restrict__ W   = d ? bWih : fWih;
    const int*   __restrict__ tok = g_tok + d * SS * BB;
    const float* __restrict__ bih = d ? bbih : fbih;
    const float* __restrict__ bhh = d ? bbhh : fbhh;

    __shared__ __align__(16) float2 As2[32][66];  // [k][m] dup pairs, padded
    __shared__ __align__(16) float  Bs[32][64];   // [k][n]
    __shared__ int ts[64];

    const int tid = threadIdx.x;
    if (tid < 64) ts[tid] = tok[n0 + tid];
    __syncthreads();

    unsigned long long acc[4][2] = {};

    const int ty = tid >> 4;      // m quad
    const int tx = tid & 15;      // n quad

    for (int k0 = 0; k0 < EE; k0 += 32) {
        // A tile (transpose + duplicate): read W rows coalesced along e
#pragma unroll
        for (int q = 0; q < 2; q++) {
            int idx = tid + q * 256;
            int m  = idx >> 3;             // 0..63
            int kq = idx & 7;              // 0..7
            float4 v = *(const float4*)(W + (size_t)(g0 + m) * EE + k0 + kq * 4);
            As2[kq * 4 + 0][m] = make_float2(v.x, v.x);
            As2[kq * 4 + 1][m] = make_float2(v.y, v.y);
            As2[kq * 4 + 2][m] = make_float2(v.z, v.z);
            As2[kq * 4 + 3][m] = make_float2(v.w, v.w);
        }
        // B tile: gather embedding rows
#pragma unroll
        for (int q = 0; q < 2; q++) {
            int idx = tid + q * 256;
            int n  = idx & 63;
            int kq = idx >> 6;             // 0..7
            float4 v = *(const float4*)(emb + (size_t)ts[n] * EE + k0 + kq * 4);
            Bs[kq * 4 + 0][n] = v.x;
            Bs[kq * 4 + 1][n] = v.y;
            Bs[kq * 4 + 2][n] = v.z;
            Bs[kq * 4 + 3][n] = v.w;
        }
        __syncthreads();
#pragma unroll
        for (int k = 0; k < 32; k++) {
            ulonglong2 a01 = *(const ulonglong2*)&As2[k][ty * 4];
            ulonglong2 a23 = *(const ulonglong2*)&As2[k][ty * 4 + 2];
            ulonglong2 bb  = *(const ulonglong2*)&Bs[k][tx * 4];
            fma2(acc[0][0], a01.x, bb.x); fma2(acc[0][1], a01.x, bb.y);
            fma2(acc[1][0], a01.y, bb.x); fma2(acc[1][1], a01.y, bb.y);
            fma2(acc[2][0], a23.x, bb.x); fma2(acc[2][1], a23.x, bb.y);
            fma2(acc[3][0], a23.y, bb.x); fma2(acc[3][1], a23.y, bb.y);
        }
        __syncthreads();
    }

    int t  = (n0 >> 5) + ((tx * 4) >> 5);
    int b0 = (tx * 4) & 31;
    size_t base_d = (size_t)d * SS * G4 * BB;
#pragma unroll
    for (int i = 0; i < 4; i++) {
        int grow = g0 + ty * 4 + i;
        float bias = bih[grow] + bhh[grow];
        float2 lo = unpk(acc[i][0]);
        float2 hi = unpk(acc[i][1]);
        float4 r = make_float4(lo.x + bias, lo.y + bias, hi.x + bias, hi.y + bias);
        *(float4*)&g_xg[base_d + (((size_t)t * G4 + grow) << 5) + b0] = r;
    }
}

// ---------------- persistent recurrence (k-split-8, f32x2 row-pairs) ----------
// 128 blocks: d = bx>>6, blk = bx&63. Block owns hidden units 4*blk..4*blk+3
// (16 gate rows). Warp w owns k in [32w, 32w+32); thread covers all 16 rows
// for one batch lane. h streamed through the crossbar exactly once per step.
__global__ __launch_bounds__(256) void k_rec(const float* __restrict__ fWhh,
                                             const float* __restrict__ bWhh)
{
    const int d   = blockIdx.x >> 6;
    const int blk = blockIdx.x & 63;
    const float* __restrict__ Whh = d ? bWhh : fWhh;

    __shared__ __align__(16) float4 wp4[4][256];   // 16KB: [rg][k] = rows 4rg..4rg+3
    __shared__ __align__(16) float  hs[HH * BB];   // 32KB: [k*32+b]
    float2* psum = (float2*)hs;                    // alias: [ (s*8+p)*32+b ] 16KB
    float2* gbf  = (float2*)(hs + 4096);           // alias: [ p*32+b ] 2KB

    const int tid  = threadIdx.x;
    const int s    = tid >> 5;      // warp id = k chunk
    const int lane = tid & 31;      // batch

    // preload W_hh slice as row-quad float4s: component c = gate c of unit rg
    for (int idx = tid; idx < 1024; idx += 256) {
        int rg = idx >> 8, k = idx & 255;
        int gb4 = blk * 4 + rg;
        wp4[rg][k] = make_float4(Whh[(size_t)(0 * HH + gb4) * HH + k],
                                 Whh[(size_t)(1 * HH + gb4) * HH + k],
                                 Whh[(size_t)(2 * HH + gb4) * HH + k],
                                 Whh[(size_t)(3 * HH + gb4) * HH + k]);
    }

    const float* __restrict__ xgd = g_xg + (size_t)d * SS * G4 * BB;
    float* __restrict__ hhd = g_hh + (size_t)d * SS * BB * HH;
    unsigned* cnt = &g_cnt[d];

    // reduce-phase row pair for this thread: l = 2p, 2p+1
    const int p  = tid >> 5;
    const int grow0 = ((2 * p) & 3) * HH + blk * 4 + ((2 * p) >> 2);
    const int grow1 = ((2 * p + 1) & 3) * HH + blk * 4 + ((2 * p + 1) >> 2);

    // nonlinearity thread mapping (tid < 128): unit u, batch cb
    const int u  = (tid >> 5) & 3;
    const int cb = lane;
    const int ck = blk * 4 + u;
    float c = 0.0f;

    // prefetch xg(t=0)
    float xa0 = xgd[((size_t)grow0 << 5) + lane];
    float xa1 = xgd[((size_t)grow1 << 5) + lane];

    const int kbase = s * 32;

    for (int t = 0; t < SS; t++) {
        const float* rbuf = g_hprev[d][t & 1];
        float*       wbuf = g_hprev[d][(t + 1) & 1];

        // stage h(t-1) into smem
#pragma unroll
        for (int q = 0; q < 8; q++) {
            int i4 = tid + q * 256;
            *(float4*)&hs[i4 * 4] = *(const float4*)(rbuf + i4 * 4);
        }
        __syncthreads();

        unsigned long long a0 = 0, a1 = 0, a2 = 0, a3 = 0,
                           a4 = 0, a5 = 0, a6 = 0, a7 = 0;
#pragma unroll 8
        for (int kk = 0; kk < 32; kk++) {
            int k = kbase + kk;
            unsigned long long hd = dup2(hs[(k << 5) + lane]);
            ulonglong2 w01 = *(const ulonglong2*)&wp4[0][k];
            ulonglong2 w23 = *(const ulonglong2*)&wp4[1][k];
            ulonglong2 w45 = *(const ulonglong2*)&wp4[2][k];
            ulonglong2 w67 = *(const ulonglong2*)&wp4[3][k];
            fma2(a0, w01.x, hd); fma2(a1, w01.y, hd);
            fma2(a2, w23.x, hd); fma2(a3, w23.y, hd);
            fma2(a4, w45.x, hd); fma2(a5, w45.y, hd);
            fma2(a6, w67.x, hd); fma2(a7, w67.y, hd);
        }
        __syncthreads();   // all hs reads done -> safe to alias-write psum

        {
            unsigned long long* ps = (unsigned long long*)psum;
            ps[(s * 8 + 0) * 32 + lane] = a0;
            ps[(s * 8 + 1) * 32 + lane] = a1;
            ps[(s * 8 + 2) * 32 + lane] = a2;
            ps[(s * 8 + 3) * 32 + lane] = a3;
            ps[(s * 8 + 4) * 32 + lane] = a4;
            ps[(s * 8 + 5) * 32 + lane] = a5;
            ps[(s * 8 + 6) * 32 + lane] = a6;
            ps[(s * 8 + 7) * 32 + lane] = a7;
        }
        __syncthreads();

        // reduce across the 8 k-chunks; add xg; publish gate pairs
        {
            float ga = xa0, gb = xa1;
#pragma unroll
            for (int s2 = 0; s2 < 8; s2++) {
                float2 v = psum[(s2 * 8 + p) * 32 + lane];
                ga += v.x; gb += v.y;
            }
            gbf[p * 32 + lane] = make_float2(ga, gb);
        }
        // prefetch next step's xg while gates settle
        {
            int tn = (t + 1 < SS) ? (t + 1) : t;
            xa0 = xgd[(((size_t)tn * G4 + grow0) << 5) + lane];
            xa1 = xgd[(((size_t)tn * G4 + grow1) << 5) + lane];
        }
        __syncthreads();

        if (tid < 128) {
            float2 g01 = gbf[(2 * u) * 32 + cb];      // i, f
            float2 g23 = gbf[(2 * u + 1) * 32 + cb];  // g, o
            c = sigm(g01.y) * c + sigm(g01.x) * tanhf(g23.x);
            float h = sigm(g23.y) * tanhf(c);
            wbuf[(ck << 5) + cb] = h;
            hhd[(((size_t)t * BB + cb) << 8) + ck] = h;
        }
        __syncthreads();
        if (tid == 0) {
            asm volatile("red.release.gpu.add.u32 [%0], %1;" :: "l"(cnt), "r"(1u) : "memory");
            unsigned target = 64u * (unsigned)(t + 1);
            unsigned v;
            do {
                asm volatile("ld.acquire.gpu.u32 %0, [%1];" : "=r"(v) : "l"(cnt) : "memory");
            } while (v < target);
        }
        __syncthreads();
    }
}

// ---------------- output gather -----------------------------------------------
__global__ __launch_bounds__(128) void k_gather(float* __restrict__ out, int rows)
{
    int j = blockIdx.x;
    int b = blockIdx.y;
    int tid = threadIdx.x;
    int cnt = g_counts[b];
    size_t orow = ((size_t)b * rows + j) * 512;
    float4 v = make_float4(0.f, 0.f, 0.f, 0.f);
    if (j < cnt) {
        if (tid < 64) {
            int tf = g_order[b * SS + j];
            v = *(const float4*)(g_hh + (((size_t)tf * BB + b) << 8) + tid * 4);
        } else {
            int tb = g_order[b * SS + (cnt - 1 - j)];
            v = *(const float4*)(g_hh + ((((size_t)SS + tb) * BB + b) << 8) + (tid - 64) * 4);
        }
    }
    *(float4*)(out + orow + tid * 4) = v;
}

// ---------------- launch ------------------------------------------------------
extern "C" void kernel_launch(void* const* d_in, const int* in_sizes, int n_in,
                              void* d_out, int out_size)
{
    const int*   inputs = (const int*)d_in[0];
    const int*   seqlen = (const int*)d_in[1];
    const int*   fmask  = (const int*)d_in[2];
    // d_in[3] = bmask (unused by the reference math)
    int base = (in_sizes[4] == 1) ? 5 : 4;   // skip out_seq_length scalar if present
    const float* emb   = (const float*)d_in[base + 0];
    const float* f_Wih = (const float*)d_in[base + 1];
    const float* f_Whh = (const float*)d_in[base + 2];
    const float* f_bih = (const float*)d_in[base + 3];
    const float* f_bhh = (const float*)d_in[base + 4];
    const float* b_Wih = (const float*)d_in[base + 5];
    const float* b_Whh = (const float*)d_in[base + 6];
    const float* b_bih = (const float*)d_in[base + 7];
    const float* b_bhh = (const float*)d_in[base + 8];
    (void)n_in;

    int rows = out_size / (BB * 512);        // out_seq_length (== S here)

    k_prep<<<BB, SS>>>(inputs, seqlen, fmask);
    k_gemm<<<dim3(512, 16, 2), 256>>>(emb, f_Wih, b_Wih, f_bih, f_bhh, b_bih, b_bhh);
    k_rec<<<128, 256>>>(f_Whh, b_Whh);
    k_gather<<<dim3(rows, BB), 128>>>((float*)d_out, rows);
}

// round 8
// speedup vs baseline: 1.3490x; 1.3222x over previous
#include <cuda_runtime.h>
#include <cuda_bf16.h>
#include <math.h>

// Problem constants
#define BB 32
#define SS 1024
#define EE 512
#define HH 256
#define G4 1024          // 4*H

// ---------------- static scratch (no allocations) ----------------
__device__ float    g_xg[(size_t)2 * SS * G4 * BB];     // [d][t][g][b]
__device__ float    g_WT[(size_t)2 * EE * G4];          // [d][e][g]
__device__ int      g_tok[2 * SS * BB];                 // [d][t*32+b]
__device__ int      g_j[2 * SS * BB];                   // [d][t*32+b] out row or -1
__device__ float    g_hprev[2][2][HH * BB];             // [d][buf][k*32+b]
__device__ unsigned g_cnt[2];

__device__ __forceinline__ float sigm(float x) { return 1.0f / (1.0f + __expf(-x)); }

__device__ __forceinline__ void fma2(unsigned long long &d,
                                     unsigned long long a, unsigned long long b) {
    asm("fma.rn.f32x2 %0, %1, %2, %0;" : "+l"(d) : "l"(a), "l"(b));
}
__device__ __forceinline__ unsigned long long dup2(float x) {
    unsigned long long r; asm("mov.b64 %0, {%1, %1};" : "=l"(r) : "f"(x)); return r;
}
__device__ __forceinline__ float2 unpk(unsigned long long v) {
    float2 r; asm("mov.b64 {%0, %1}, %2;" : "=f"(r.x), "=f"(r.y) : "l"(v)); return r;
}

// ---------------- prep: inverse permutation, token arrays, state reset --------
__global__ __launch_bounds__(1024) void k_prep(const int* __restrict__ inputs,
                                               const int* __restrict__ seqlen,
                                               const int* __restrict__ fmask)
{
    int b = blockIdx.x;
    int t = threadIdx.x;
    __shared__ int sc[SS];
    int m = (fmask[b * SS + t] != 0) ? 1 : 0;
    sc[t] = m;
    __syncthreads();
    for (int off = 1; off < SS; off <<= 1) {
        int v = (t >= off) ? sc[t - off] : 0;
        __syncthreads();
        sc[t] += v;
        __syncthreads();
    }
    int r   = sc[t];          // inclusive rank
    int cnt = sc[SS - 1];
    g_j[t * BB + b]           = m ? (r - 1)   : -1;   // fwd out row
    g_j[SS * BB + t * BB + b] = m ? (cnt - r) : -1;   // bwd out row

    int len = seqlen[b];
    g_tok[t * BB + b] = inputs[b * SS + t];
    g_tok[SS * BB + t * BB + b] = (t < len) ? inputs[b * SS + (len - 1 - t)] : 0;

    if (b == 0) {
        for (int i = t; i < 2 * HH * BB; i += 1024) {
            int d = i / (HH * BB);
            g_hprev[d][0][i - d * HH * BB] = 0.0f;
        }
        if (t < 2) g_cnt[t] = 0u;
    }
}

// ---------------- tiled transpose W_ih[g][e] -> WT[e][g] -----------------------
__global__ __launch_bounds__(256) void k_wt(const float* __restrict__ fW,
                                            const float* __restrict__ bW)
{
    __shared__ float tile[32][33];
    int d  = blockIdx.z;
    int g0 = blockIdx.x * 32;
    int e0 = blockIdx.y * 32;
    const float* W = d ? bW : fW;
    int tx = threadIdx.x & 31, ty = threadIdx.x >> 5;  // 32 x 8
#pragma unroll
    for (int j = 0; j < 4; j++) {
        int g = g0 + ty + j * 8;
        tile[ty + j * 8][tx] = W[(size_t)g * EE + e0 + tx];
    }
    __syncthreads();
#pragma unroll
    for (int j = 0; j < 4; j++) {
        int e = e0 + ty + j * 8;
        g_WT[(size_t)d * EE * G4 + (size_t)e * G4 + g0 + tx] = tile[tx][ty + j * 8];
    }
}

// ---------------- xg GEMM: 128x128 tile, 8x8 micro, f32x2, fused gather --------
// C[d][t][g][b] = sum_e WT[e][g] * emb[tok[n]][e] + bih[g] + bhh[g],  n = t*32+b
__global__ __launch_bounds__(256) void k_gemm(
    const float* __restrict__ emb,
    const float* __restrict__ fbih, const float* __restrict__ fbhh,
    const float* __restrict__ bbih, const float* __restrict__ bbhh)
{
    const int d  = blockIdx.z;
    const int g0 = blockIdx.y * 128;
    const int n0 = blockIdx.x * 128;
    const float* __restrict__ WT  = g_WT + (size_t)d * EE * G4;
    const int*   __restrict__ tok = g_tok + d * SS * BB;
    const float* __restrict__ bih = d ? bbih : fbih;
    const float* __restrict__ bhh = d ? bbhh : fbhh;

    __shared__ __align__(16) float As[16 * 128];      // [k][m]
    __shared__ __align__(16) float Bs[16 * 132];      // [k][n] padded
    __shared__ int ts[128];

    const int tid = threadIdx.x;
    if (tid < 128) ts[tid] = tok[n0 + tid];
    __syncthreads();

    const int ty = tid >> 4;      // 0..15 (m octet)
    const int tx = tid & 15;      // 0..15 (n octet)

    // per-thread load coordinates
    const int akr = tid >> 5;            // 0..7  (k row, +8 for second)
    const int am4 = (tid & 31) * 4;      // m offset
    const int bn  = tid >> 2;            // 0..63 (n, +64 for second)
    const int bk4 = (tid & 3) * 4;       // k offset
    const size_t arow0 = (size_t)akr * G4 + g0 + am4;
    const size_t arow1 = (size_t)(akr + 8) * G4 + g0 + am4;
    const size_t brow0 = (size_t)ts[bn] * EE + bk4;
    const size_t brow1 = (size_t)ts[bn + 64] * EE + bk4;

    unsigned long long acc[8][4] = {};

    float4 pa0 = *(const float4*)(WT + arow0);
    float4 pa1 = *(const float4*)(WT + arow1);
    float4 pb0 = *(const float4*)(emb + brow0);
    float4 pb1 = *(const float4*)(emb + brow1);

    for (int kt = 0; kt < 32; kt++) {
        // store prefetched regs -> smem
        *(float4*)&As[akr * 128 + am4]       = pa0;
        *(float4*)&As[(akr + 8) * 128 + am4] = pa1;
        Bs[(bk4 + 0) * 132 + bn] = pb0.x;  Bs[(bk4 + 1) * 132 + bn] = pb0.y;
        Bs[(bk4 + 2) * 132 + bn] = pb0.z;  Bs[(bk4 + 3) * 132 + bn] = pb0.w;
        Bs[(bk4 + 0) * 132 + bn + 64] = pb1.x;  Bs[(bk4 + 1) * 132 + bn + 64] = pb1.y;
        Bs[(bk4 + 2) * 132 + bn + 64] = pb1.z;  Bs[(bk4 + 3) * 132 + bn + 64] = pb1.w;
        __syncthreads();

        if (kt < 31) {
            int k0 = (kt + 1) * 16;
            pa0 = *(const float4*)(WT + (size_t)k0 * G4 + arow0);
            pa1 = *(const float4*)(WT + (size_t)k0 * G4 + arow1);
            pb0 = *(const float4*)(emb + brow0 + k0);
            pb1 = *(const float4*)(emb + brow1 + k0);
        }

#pragma unroll
        for (int k = 0; k < 16; k++) {
            float4 af0 = *(float4*)&As[k * 128 + ty * 8];
            float4 af1 = *(float4*)&As[k * 128 + ty * 8 + 4];
            ulonglong2 bq0 = *(ulonglong2*)&Bs[k * 132 + tx * 8];
            ulonglong2 bq1 = *(ulonglong2*)&Bs[k * 132 + tx * 8 + 4];
            unsigned long long ad[8];
            ad[0] = dup2(af0.x); ad[1] = dup2(af0.y);
            ad[2] = dup2(af0.z); ad[3] = dup2(af0.w);
            ad[4] = dup2(af1.x); ad[5] = dup2(af1.y);
            ad[6] = dup2(af1.z); ad[7] = dup2(af1.w);
#pragma unroll
            for (int i = 0; i < 8; i++) {
                fma2(acc[i][0], ad[i], bq0.x);
                fma2(acc[i][1], ad[i], bq0.y);
                fma2(acc[i][2], ad[i], bq1.x);
                fma2(acc[i][3], ad[i], bq1.y);
            }
        }
        __syncthreads();
    }

    // epilogue: n block of 8 stays inside one t (8 | 32)
    int nb = n0 + tx * 8;
    int t  = nb >> 5;
    int b0 = nb & 31;
    size_t base_d = (size_t)d * SS * G4 * BB;
#pragma unroll
    for (int i = 0; i < 8; i++) {
        int grow = g0 + ty * 8 + i;
        float bias = bih[grow] + bhh[grow];
        float2 p0 = unpk(acc[i][0]);
        float2 p1 = unpk(acc[i][1]);
        float2 p2 = unpk(acc[i][2]);
        float2 p3 = unpk(acc[i][3]);
        size_t off = base_d + (((size_t)t * G4 + grow) << 5) + b0;
        *(float4*)&g_xg[off]     = make_float4(p0.x + bias, p0.y + bias, p1.x + bias, p1.y + bias);
        *(float4*)&g_xg[off + 4] = make_float4(p2.x + bias, p2.y + bias, p3.x + bias, p3.y + bias);
    }
}

// ---------------- persistent recurrence (k-split-8, writes d_out directly) ----
// 128 blocks: d = bx>>6, blk = bx&63. Block owns hidden units 4*blk..4*blk+3.
// Dynamic smem: wp4 16K | hs 32K | psum 16K | gbf 2K | hstage 0.5K
__global__ __launch_bounds__(256) void k_rec(const float* __restrict__ fWhh,
                                             const float* __restrict__ bWhh,
                                             float* __restrict__ out, int rows)
{
    extern __shared__ __align__(16) char dsm[];
    float4 (*wp4)[256] = (float4(*)[256])dsm;
    float*  hs     = (float*)(dsm + 16384);
    float2* psum   = (float2*)(dsm + 49152);
    float2* gbf    = (float2*)(dsm + 65536);
    float*  hstage = (float*)(dsm + 67584);

    const int d   = blockIdx.x >> 6;
    const int blk = blockIdx.x & 63;
    const float* __restrict__ Whh = d ? bWhh : fWhh;

    const int tid  = threadIdx.x;
    const int s    = tid >> 5;      // warp id = k chunk
    const int lane = tid & 31;

    for (int idx = tid; idx < 1024; idx += 256) {
        int rg = idx >> 8, k = idx & 255;
        int gb4 = blk * 4 + rg;
        wp4[rg][k] = make_float4(Whh[(size_t)(0 * HH + gb4) * HH + k],
                                 Whh[(size_t)(1 * HH + gb4) * HH + k],
                                 Whh[(size_t)(2 * HH + gb4) * HH + k],
                                 Whh[(size_t)(3 * HH + gb4) * HH + k]);
    }

    const float* __restrict__ xgd = g_xg + (size_t)d * SS * G4 * BB;
    const int*   __restrict__ jd_arr = g_j + d * SS * BB;
    unsigned* cnt = &g_cnt[d];

    const int p  = tid >> 5;
    const int grow0 = ((2 * p) & 3) * HH + blk * 4 + ((2 * p) >> 2);
    const int grow1 = ((2 * p + 1) & 3) * HH + blk * 4 + ((2 * p + 1) >> 2);

    const int u  = (tid >> 5) & 3;   // nonlin unit (tid<128)
    const int ck = blk * 4 + u;
    float c = 0.0f;

    float xa0 = xgd[((size_t)grow0 << 5) + lane];
    float xa1 = xgd[((size_t)grow1 << 5) + lane];

    const int kbase = s * 32;
    const size_t outbase = (size_t)d * 256 + blk * 4;

    for (int t = 0; t < SS; t++) {
        const float* rbuf = g_hprev[d][t & 1];
        float*       wbuf = g_hprev[d][(t + 1) & 1];

#pragma unroll
        for (int q = 0; q < 8; q++) {
            int i4 = tid + q * 256;
            *(float4*)&hs[i4 * 4] = *(const float4*)(rbuf + i4 * 4);
        }
        __syncthreads();                                  // S1

        unsigned long long a0 = 0, a1 = 0, a2 = 0, a3 = 0,
                           a4 = 0, a5 = 0, a6 = 0, a7 = 0;
#pragma unroll 8
        for (int kk = 0; kk < 32; kk++) {
            int k = kbase + kk;
            unsigned long long hd = dup2(hs[(k << 5) + lane]);
            ulonglong2 w01 = *(const ulonglong2*)&wp4[0][k];
            ulonglong2 w23 = *(const ulonglong2*)&wp4[1][k];
            ulonglong2 w45 = *(const ulonglong2*)&wp4[2][k];
            ulonglong2 w67 = *(const ulonglong2*)&wp4[3][k];
            fma2(a0, w01.x, hd); fma2(a1, w01.y, hd);
            fma2(a2, w23.x, hd); fma2(a3, w23.y, hd);
            fma2(a4, w45.x, hd); fma2(a5, w45.y, hd);
            fma2(a6, w67.x, hd); fma2(a7, w67.y, hd);
        }
        {
            unsigned long long* ps = (unsigned long long*)psum;
            ps[(s * 8 + 0) * 32 + lane] = a0;
            ps[(s * 8 + 1) * 32 + lane] = a1;
            ps[(s * 8 + 2) * 32 + lane] = a2;
            ps[(s * 8 + 3) * 32 + lane] = a3;
            ps[(s * 8 + 4) * 32 + lane] = a4;
            ps[(s * 8 + 5) * 32 + lane] = a5;
            ps[(s * 8 + 6) * 32 + lane] = a6;
            ps[(s * 8 + 7) * 32 + lane] = a7;
        }
        __syncthreads();                                  // S2

        {
            float ga = xa0, gb = xa1;
#pragma unroll
            for (int s2 = 0; s2 < 8; s2++) {
                float2 v = psum[(s2 * 8 + p) * 32 + lane];
                ga += v.x; gb += v.y;
            }
            gbf[p * 32 + lane] = make_float2(ga, gb);
        }
        {   // prefetch next step's xg
            int tn = (t + 1 < SS) ? (t + 1) : t;
            xa0 = xgd[(((size_t)tn * G4 + grow0) << 5) + lane];
            xa1 = xgd[(((size_t)tn * G4 + grow1) << 5) + lane];
        }
        __syncthreads();                                  // S3

        if (tid < 128) {
            float2 g01 = gbf[(2 * u) * 32 + lane];        // i, f
            float2 g23 = gbf[(2 * u + 1) * 32 + lane];    // g, o
            c = sigm(g01.y) * c + sigm(g01.x) * tanhf(g23.x);
            float h = sigm(g23.y) * tanhf(c);
            wbuf[(ck << 5) + lane] = h;
            hstage[lane * 4 + u] = h;
        }
        __syncthreads();                                  // S4

        if (tid < 32) {
            int jo = jd_arr[t * BB + tid];
            if (jo >= 0 && jo < rows) {
                float4 hv = *(float4*)&hstage[tid * 4];
                *(float4*)(out + ((size_t)tid * rows + jo) * 512 + outbase) = hv;
            }
        } else if (tid == 32) {
            asm volatile("red.release.gpu.add.u32 [%0], %1;" :: "l"(cnt), "r"(1u) : "memory");
            unsigned target = 64u * (unsigned)(t + 1);
            unsigned v;
            do {
                asm volatile("ld.acquire.gpu.u32 %0, [%1];" : "=r"(v) : "l"(cnt) : "memory");
            } while (v < target);
        }
        __syncthreads();                                  // S5
    }
}

// ---------------- launch ------------------------------------------------------
extern "C" void kernel_launch(void* const* d_in, const int* in_sizes, int n_in,
                              void* d_out, int out_size)
{
    const int*   inputs = (const int*)d_in[0];
    const int*   seqlen = (const int*)d_in[1];
    const int*   fmask  = (const int*)d_in[2];
    // d_in[3] = bmask (unused by the reference math)
    int base = (in_sizes[4] == 1) ? 5 : 4;   // skip out_seq_length scalar if present
    const float* emb   = (const float*)d_in[base + 0];
    const float* f_Wih = (const float*)d_in[base + 1];
    const float* f_Whh = (const float*)d_in[base + 2];
    const float* f_bih = (const float*)d_in[base + 3];
    const float* f_bhh = (const float*)d_in[base + 4];
    const float* b_Wih = (const float*)d_in[base + 5];
    const float* b_Whh = (const float*)d_in[base + 6];
    const float* b_bih = (const float*)d_in[base + 7];
    const float* b_bhh = (const float*)d_in[base + 8];
    (void)n_in;

    int rows = out_size / (BB * 512);        // out_seq_length

    static int smem_set = 0;
    if (!smem_set) {
        cudaFuncSetAttribute(k_rec, cudaFuncAttributeMaxDynamicSharedMemorySize, 68096);
        smem_set = 1;
    }

    cudaMemsetAsync(d_out, 0, (size_t)out_size * sizeof(float), 0);
    k_prep<<<BB, SS>>>(inputs, seqlen, fmask);
    k_wt<<<dim3(32, 16, 2), 256>>>(f_Wih, b_Wih);
    k_gemm<<<dim3(256, 8, 2), 256>>>(emb, f_bih, f_bhh, b_bih, b_bhh);
    k_rec<<<128, 256, 68096>>>(f_Whh, b_Whh, (float*)d_out, rows);
}